// round 3
// baseline (speedup 1.0000x reference)
#include <cuda_runtime.h>
#include <cstdint>
#include <math.h>

#define NMAX 50048
#define EMAX 650000
#define FD   128
#define GG   64
#define TILE_R 64

// ---- static scratch (no allocations allowed) ----
__device__ float d_bufA[NMAX * FD];   // GEMM output m' = (XW) * dinv[row]
__device__ float d_bufB[NMAX * FD];   // h1
__device__ float d_dinv[NMAX];
__device__ float d_gpool[GG * FD];
__device__ int   d_degi[NMAX];
__device__ int   d_off[NMAX + 1];
__device__ int   d_cursor[NMAX];
__device__ int   d_csr[EMAX];

// ---------------- degree count (int) ----------------
__global__ void deg_count(const int* __restrict__ dst, int* __restrict__ degi, int E) {
    int i = blockIdx.x * blockDim.x + threadIdx.x;
    if (i < E) atomicAdd(&degi[dst[i]], 1);
}

// ---------------- offsets (exclusive scan) + cursor + dinv ----------------
__global__ void build_offsets(const int* __restrict__ degi, int* __restrict__ off,
                              int* __restrict__ cursor, float* __restrict__ dinv, int n) {
    __shared__ int wsum[32];
    int tid = threadIdx.x;                    // 1024 threads, single block
    int per = (n + 1023) >> 10;
    int start = tid * per;
    int end = start + per; if (end > n) end = n;

    int s = 0;
    for (int i = start; i < end; i++) s += degi[i];

    int lane = tid & 31, wid = tid >> 5;
    int v = s;
    #pragma unroll
    for (int o = 1; o < 32; o <<= 1) {
        int t = __shfl_up_sync(0xffffffffu, v, o);
        if (lane >= o) v += t;
    }
    if (lane == 31) wsum[wid] = v;
    __syncthreads();
    if (wid == 0) {
        int w = wsum[lane];
        #pragma unroll
        for (int o = 1; o < 32; o <<= 1) {
            int t = __shfl_up_sync(0xffffffffu, w, o);
            if (lane >= o) w += t;
        }
        wsum[lane] = w;
    }
    __syncthreads();

    int base = v - s + (wid ? wsum[wid - 1] : 0);   // exclusive prefix
    int run = base;
    for (int i = start; i < end; i++) {
        off[i] = run; cursor[i] = run;
        dinv[i] = rsqrtf((float)(degi[i] + 1));     // +1 self loop
        run += degi[i];
    }
    if (start < n && end == n) off[n] = run;
}

// ---------------- fill CSR ----------------
__global__ void fill_csr(const int* __restrict__ ei, int* __restrict__ cursor,
                         int* __restrict__ csr, int E) {
    int i = blockIdx.x * blockDim.x + threadIdx.x;
    if (i >= E) return;
    int s = ei[i];
    int d = ei[E + i];
    int p = atomicAdd(&cursor[d], 1);
    csr[p] = s;
}

// ---------------- GEMM: Y[r,:] = (X[r,:] @ W) * dinv[r] ----------------
// persistent blocks, W in smem once, X tiles double-buffered via cp.async,
// 4 rows x 8 cols per thread using fma.rn.f32x2 (packed dual FMA).
__device__ __forceinline__ void load_tile_async(float* dst, const float* X, int row0, int n) {
    #pragma unroll
    for (int t = 0; t < 8; t++) {
        int idx = threadIdx.x + t * 256;      // float4 index in 64x128 tile
        int r = idx >> 5;
        if (row0 + r < n) {
            unsigned int sa = (unsigned int)__cvta_generic_to_shared(dst + idx * 4);
            const float4* g = (const float4*)X + (size_t)(row0 + r) * 32 + (idx & 31);
            asm volatile("cp.async.cg.shared.global [%0], [%1], 16;\n" :: "r"(sa), "l"(g));
        }
    }
    asm volatile("cp.async.commit_group;\n" ::: "memory");
}

__global__ void __launch_bounds__(256, 1)
gemm128(const float* __restrict__ X, const float* __restrict__ W,
        const float* __restrict__ dinv, float* __restrict__ Y, int n, int ntiles) {
    extern __shared__ float sh[];
    float* Wsh = sh;                          // 128*128 floats = 64KB
    float* Xbuf0 = sh + 16384;                // 64*128 = 32KB
    float* Xbuf1 = Xbuf0 + 8192;              // 32KB

    for (int i = threadIdx.x; i < 16384; i += 256) Wsh[i] = W[i];

    const int tx = threadIdx.x & 15;          // 16 col groups
    const int ty = threadIdx.x >> 4;          // 16 row groups
    const int c0 = tx * 8;
    const int r0 = ty * 4;

    int t0 = blockIdx.x;
    if (t0 < ntiles) load_tile_async(Xbuf0, X, t0 * TILE_R, n);

    int p = 0;
    for (int tile = t0; tile < ntiles; tile += gridDim.x, p ^= 1) {
        float* cur = p ? Xbuf1 : Xbuf0;
        float* nxt = p ? Xbuf0 : Xbuf1;
        int nt = tile + gridDim.x;
        if (nt < ntiles) load_tile_async(nxt, X, nt * TILE_R, n);
        else asm volatile("cp.async.commit_group;\n" ::: "memory");
        asm volatile("cp.async.wait_group 1;\n" ::: "memory");
        __syncthreads();

        unsigned long long acc[4][4];
        #pragma unroll
        for (int j = 0; j < 4; j++)
            #pragma unroll
            for (int q = 0; q < 4; q++) acc[j][q] = 0ull;

        #pragma unroll 8
        for (int k4 = 0; k4 < FD; k4 += 4) {
            float4 xv[4];
            #pragma unroll
            for (int j = 0; j < 4; j++)
                xv[j] = *(const float4*)(cur + (r0 + j) * FD + k4);
            #pragma unroll
            for (int kk = 0; kk < 4; kk++) {
                const unsigned long long* wr =
                    (const unsigned long long*)(Wsh + (k4 + kk) * FD + c0);
                unsigned long long w0 = wr[0], w1 = wr[1], w2 = wr[2], w3 = wr[3];
                #pragma unroll
                for (int j = 0; j < 4; j++) {
                    float xs = (kk == 0) ? xv[j].x : (kk == 1) ? xv[j].y
                             : (kk == 2) ? xv[j].z : xv[j].w;
                    unsigned int xb = __float_as_uint(xs);
                    unsigned long long xd;
                    asm("mov.b64 %0, {%1, %1};" : "=l"(xd) : "r"(xb));
                    asm("fma.rn.f32x2 %0, %1, %2, %0;" : "+l"(acc[j][0]) : "l"(xd), "l"(w0));
                    asm("fma.rn.f32x2 %0, %1, %2, %0;" : "+l"(acc[j][1]) : "l"(xd), "l"(w1));
                    asm("fma.rn.f32x2 %0, %1, %2, %0;" : "+l"(acc[j][2]) : "l"(xd), "l"(w2));
                    asm("fma.rn.f32x2 %0, %1, %2, %0;" : "+l"(acc[j][3]) : "l"(xd), "l"(w3));
                }
            }
        }

        int row0 = tile * TILE_R;
        #pragma unroll
        for (int j = 0; j < 4; j++) {
            int r = row0 + r0 + j;
            if (r < n) {
                float s = dinv[r];
                float o[8];
                #pragma unroll
                for (int q = 0; q < 4; q++) {
                    o[2*q]   = __uint_as_float((unsigned int)acc[j][q]) * s;
                    o[2*q+1] = __uint_as_float((unsigned int)(acc[j][q] >> 32)) * s;
                }
                float4* yp = (float4*)(Y + (size_t)r * FD + c0);
                yp[0] = make_float4(o[0], o[1], o[2], o[3]);
                yp[1] = make_float4(o[4], o[5], o[6], o[7]);
            }
        }
        __syncthreads();
    }
}

// ---------------- gather: one warp per node ----------------
// agg[d] = dinv[d] * (m'[d] + sum_{e: dst=d} m'[src]);  h = relu(agg + b)
// if gpool != nullptr: atomicMax into pooled features instead of storing h.
__global__ void gather(const float4* __restrict__ m4, const int* __restrict__ csr,
                       const int* __restrict__ off, const float* __restrict__ dinv,
                       const float* __restrict__ bias, float* __restrict__ hout,
                       const int* __restrict__ batch, float* __restrict__ gpool, int n) {
    int gid = blockIdx.x * blockDim.x + threadIdx.x;
    int node = gid >> 5;
    if (node >= n) return;
    int lane = gid & 31;

    float4 acc = __ldg(&m4[(size_t)node * 32 + lane]);   // self-loop term
    int beg = off[node], end = off[node + 1];

    for (int base = beg; base < end; base += 32) {
        int rem = end - base;
        int cnt = rem < 32 ? rem : 32;
        int src = (lane < cnt) ? csr[base + lane] : 0;
        int j = 0;
        for (; j + 4 <= cnt; j += 4) {
            int u0 = __shfl_sync(0xffffffffu, src, j);
            int u1 = __shfl_sync(0xffffffffu, src, j + 1);
            int u2 = __shfl_sync(0xffffffffu, src, j + 2);
            int u3 = __shfl_sync(0xffffffffu, src, j + 3);
            float4 v0 = __ldg(&m4[(size_t)u0 * 32 + lane]);
            float4 v1 = __ldg(&m4[(size_t)u1 * 32 + lane]);
            float4 v2 = __ldg(&m4[(size_t)u2 * 32 + lane]);
            float4 v3 = __ldg(&m4[(size_t)u3 * 32 + lane]);
            acc.x += (v0.x + v1.x) + (v2.x + v3.x);
            acc.y += (v0.y + v1.y) + (v2.y + v3.y);
            acc.z += (v0.z + v1.z) + (v2.z + v3.z);
            acc.w += (v0.w + v1.w) + (v2.w + v3.w);
        }
        for (; j < cnt; j++) {
            int u = __shfl_sync(0xffffffffu, src, j);
            float4 v = __ldg(&m4[(size_t)u * 32 + lane]);
            acc.x += v.x; acc.y += v.y; acc.z += v.z; acc.w += v.w;
        }
    }

    float dd = dinv[node];
    float4 bb = ((const float4*)bias)[lane];
    float4 r;
    r.x = fmaxf(fmaf(acc.x, dd, bb.x), 0.f);
    r.y = fmaxf(fmaf(acc.y, dd, bb.y), 0.f);
    r.z = fmaxf(fmaf(acc.z, dd, bb.z), 0.f);
    r.w = fmaxf(fmaf(acc.w, dd, bb.w), 0.f);

    if (gpool == nullptr) {
        ((float4*)hout)[(size_t)node * 32 + lane] = r;
    } else {
        int g = __ldg(&batch[node]);
        int* gp = (int*)(gpool + g * FD + lane * 4);
        atomicMax(gp + 0, __float_as_int(r.x));   // valid: r >= 0, pool init 0
        atomicMax(gp + 1, __float_as_int(r.y));
        atomicMax(gp + 2, __float_as_int(r.z));
        atomicMax(gp + 3, __float_as_int(r.w));
    }
}

// ---------------- head: relu(g@W3+b3) @ W4 + b4, log_softmax ----------------
__global__ void head(const float* __restrict__ g, const float* __restrict__ W3,
                     const float* __restrict__ b3, const float* __restrict__ W4,
                     const float* __restrict__ b4, float* __restrict__ out) {
    __shared__ float gs[FD];
    __shared__ float red0[4], red1[4];
    int r = blockIdx.x;
    int c = threadIdx.x;
    gs[c] = g[r * FD + c];
    __syncthreads();
    float acc = b3[c];
    #pragma unroll 8
    for (int k = 0; k < FD; k++)
        acc = fmaf(gs[k], W3[k * FD + c], acc);
    float z = acc > 0.f ? acc : 0.f;
    float p0 = z * W4[c * 2 + 0];
    float p1 = z * W4[c * 2 + 1];
    #pragma unroll
    for (int o = 16; o; o >>= 1) {
        p0 += __shfl_down_sync(0xffffffffu, p0, o);
        p1 += __shfl_down_sync(0xffffffffu, p1, o);
    }
    int wid = c >> 5;
    if ((c & 31) == 0) { red0[wid] = p0; red1[wid] = p1; }
    __syncthreads();
    if (c == 0) {
        float l0 = red0[0] + red0[1] + red0[2] + red0[3] + b4[0];
        float l1 = red1[0] + red1[1] + red1[2] + red1[3] + b4[1];
        float mx = fmaxf(l0, l1);
        float lse = mx + logf(expf(l0 - mx) + expf(l1 - mx));
        out[r * 2 + 0] = l0 - lse;
        out[r * 2 + 1] = l1 - lse;
    }
}

extern "C" void kernel_launch(void* const* d_in, const int* in_sizes, int n_in,
                              void* d_out, int out_size) {
    const float* x  = (const float*)d_in[0];
    const float* W1 = (const float*)d_in[1];
    const float* b1 = (const float*)d_in[2];
    const float* W2 = (const float*)d_in[3];
    const float* b2 = (const float*)d_in[4];
    const float* W3 = (const float*)d_in[5];
    const float* b3 = (const float*)d_in[6];
    const float* W4 = (const float*)d_in[7];
    const float* b4 = (const float*)d_in[8];
    const int*   ei = (const int*)d_in[9];
    const int* batch = (const int*)d_in[10];

    int n = in_sizes[0] / FD;
    int E = in_sizes[9] / 2;
    float* out = (float*)d_out;

    float *bufA, *bufB, *dinv, *gp;
    int *degi, *off, *cursor, *csr;
    cudaGetSymbolAddress((void**)&bufA, d_bufA);
    cudaGetSymbolAddress((void**)&bufB, d_bufB);
    cudaGetSymbolAddress((void**)&dinv, d_dinv);
    cudaGetSymbolAddress((void**)&gp,   d_gpool);
    cudaGetSymbolAddress((void**)&degi, d_degi);
    cudaGetSymbolAddress((void**)&off,  d_off);
    cudaGetSymbolAddress((void**)&cursor, d_cursor);
    cudaGetSymbolAddress((void**)&csr,  d_csr);

    static int sms = 0;
    if (sms == 0) {
        int dev = 0; cudaGetDevice(&dev);
        cudaDeviceGetAttribute(&sms, cudaDevAttrMultiProcessorCount, dev);
        if (sms <= 0) sms = 148;
    }

    const int smem = (16384 + 2 * TILE_R * FD) * (int)sizeof(float);  // 128KB
    static int attr_set = 0;
    if (!attr_set) {
        cudaFuncSetAttribute(gemm128, cudaFuncAttributeMaxDynamicSharedMemorySize, smem);
        attr_set = 1;
    }

    int ntiles = (n + TILE_R - 1) / TILE_R;
    int gather_blocks = (n * 32 + 255) / 256;

    // ---- CSR build (once, reused by both layers) ----
    cudaMemsetAsync(degi, 0, n * sizeof(int));
    deg_count<<<(E + 255) / 256, 256>>>(ei + E, degi, E);
    build_offsets<<<1, 1024>>>(degi, off, cursor, dinv, n);
    fill_csr<<<(E + 255) / 256, 256>>>(ei, cursor, csr, E);

    // ---- layer 1 ----
    gemm128<<<sms, 256, smem>>>(x, W1, dinv, bufA, n, ntiles);
    gather<<<gather_blocks, 256>>>((const float4*)bufA, csr, off, dinv, b1,
                                   bufB, nullptr, nullptr, n);

    // ---- layer 2 (pool fused) ----
    gemm128<<<sms, 256, smem>>>(bufB, W2, dinv, bufA, n, ntiles);
    cudaMemsetAsync(gp, 0, GG * FD * sizeof(float));
    gather<<<gather_blocks, 256>>>((const float4*)bufA, csr, off, dinv, b2,
                                   nullptr, batch, gp, n);

    // ---- head ----
    head<<<GG, FD>>>(gp, W3, b3, W4, b4, out);
}

// round 4
// speedup vs baseline: 1.1514x; 1.1514x over previous
#include <cuda_runtime.h>
#include <cstdint>
#include <math.h>

#define NMAX 50048
#define FD   128
#define GG   64
#define TR   128    // gemm tile rows

// ---- static scratch (no allocations allowed) ----
__device__ float d_bufA[NMAX * FD];   // messages m' = (XW)*dinv[row]
__device__ float d_bufB[NMAX * FD];   // layer-1 agg / h1
__device__ float d_bufC[NMAX * FD];   // layer-2 agg
__device__ float d_dinv[NMAX];
__device__ float d_gpool[GG * FD];

// ---------------- degree / normalization ----------------
__global__ void deg_init(float* deg, int n) {
    int i = blockIdx.x * blockDim.x + threadIdx.x;
    if (i < n) deg[i] = 1.0f;                  // self loop
}
__global__ void deg_count(const int* __restrict__ dst, float* deg, int E) {
    int i = blockIdx.x * blockDim.x + threadIdx.x;
    if (i < E) atomicAdd(&deg[dst[i]], 1.0f);
}
__global__ void deg_to_dinv(float* deg, int n) {
    int i = blockIdx.x * blockDim.x + threadIdx.x;
    if (i < n) deg[i] = rsqrtf(deg[i]);
}

// ---------------- dual-output GEMM ----------------
// Ymsg[r,:] = (X[r,:] @ W) * dinv[r];  Yself[r,:] = Ymsg[r,:] * dinv[r]
// 128-row tiles, 256 threads, 8 rows x 8 cols per thread (cols tx*4 and tx*4+64),
// W persistent in smem, X double-buffered via cp.async, fma.rn.f32x2.
__device__ __forceinline__ void load_tileX(float* dst, const float* X, int row0, int n) {
    int rows = n - row0;
    #pragma unroll
    for (int t = 0; t < 16; t++) {
        int idx = threadIdx.x + t * 256;      // float4 index in 128x128 tile
        int r = idx >> 5;
        if (r < rows) {
            unsigned int sa = (unsigned int)__cvta_generic_to_shared(dst + idx * 4);
            const float4* g = (const float4*)X + (size_t)(row0 + r) * 32 + (idx & 31);
            asm volatile("cp.async.cg.shared.global [%0], [%1], 16;\n" :: "r"(sa), "l"(g));
        }
    }
    asm volatile("cp.async.commit_group;\n" ::: "memory");
}

__global__ void __launch_bounds__(256, 1)
gemm_dual(const float* __restrict__ X, const float* __restrict__ W,
          const float* __restrict__ dinv, float* __restrict__ Ymsg,
          float* __restrict__ Yself, int n, int ntiles) {
    extern __shared__ float sh[];
    float* Wsh = sh;                          // 128*128 = 64KB
    float* Xb0 = sh + 16384;                  // 64KB
    float* Xb1 = sh + 32768;                  // 64KB

    for (int i = threadIdx.x; i < 16384; i += 256) Wsh[i] = W[i];

    const int tx = threadIdx.x & 15;
    const int ty = threadIdx.x >> 4;
    const int cA = tx * 4;                    // conflict-free: 16B stride across tx
    const int cB = cA + 64;
    const int r0 = ty * 8;

    if (blockIdx.x < ntiles) load_tileX(Xb0, X, blockIdx.x * TR, n);

    int p = 0;
    for (int tile = blockIdx.x; tile < ntiles; tile += gridDim.x, p ^= 1) {
        float* cur = p ? Xb1 : Xb0;
        float* nxt = p ? Xb0 : Xb1;
        int nt = tile + gridDim.x;
        if (nt < ntiles) load_tileX(nxt, X, nt * TR, n);
        else asm volatile("cp.async.commit_group;\n" ::: "memory");
        asm volatile("cp.async.wait_group 1;\n" ::: "memory");
        __syncthreads();

        unsigned long long acc[8][4];
        #pragma unroll
        for (int j = 0; j < 8; j++)
            #pragma unroll
            for (int q = 0; q < 4; q++) acc[j][q] = 0ull;

        #pragma unroll 2
        for (int k4 = 0; k4 < FD; k4 += 4) {
            float4 xv[8];
            #pragma unroll
            for (int j = 0; j < 8; j++)
                xv[j] = *(const float4*)(cur + (r0 + j) * FD + k4);
            #pragma unroll
            for (int kk = 0; kk < 4; kk++) {
                const float* wrow = Wsh + (k4 + kk) * FD;
                ulonglong2 wA = *(const ulonglong2*)(wrow + cA);
                ulonglong2 wB = *(const ulonglong2*)(wrow + cB);
                #pragma unroll
                for (int j = 0; j < 8; j++) {
                    float xs = (kk == 0) ? xv[j].x : (kk == 1) ? xv[j].y
                             : (kk == 2) ? xv[j].z : xv[j].w;
                    unsigned int xb = __float_as_uint(xs);
                    unsigned long long xd;
                    asm("mov.b64 %0, {%1, %1};" : "=l"(xd) : "r"(xb));
                    asm("fma.rn.f32x2 %0, %1, %2, %0;" : "+l"(acc[j][0]) : "l"(xd), "l"(wA.x));
                    asm("fma.rn.f32x2 %0, %1, %2, %0;" : "+l"(acc[j][1]) : "l"(xd), "l"(wA.y));
                    asm("fma.rn.f32x2 %0, %1, %2, %0;" : "+l"(acc[j][2]) : "l"(xd), "l"(wB.x));
                    asm("fma.rn.f32x2 %0, %1, %2, %0;" : "+l"(acc[j][3]) : "l"(xd), "l"(wB.y));
                }
            }
        }

        int row0 = tile * TR;
        #pragma unroll
        for (int j = 0; j < 8; j++) {
            int r = row0 + r0 + j;
            if (r < n) {
                float s = __ldg(&dinv[r]);
                float m[8];
                #pragma unroll
                for (int q = 0; q < 4; q++) {
                    m[2*q]   = __uint_as_float((unsigned int)acc[j][q]) * s;
                    m[2*q+1] = __uint_as_float((unsigned int)(acc[j][q] >> 32)) * s;
                }
                float4* ym = (float4*)(Ymsg + (size_t)r * FD);
                float4* ys = (float4*)(Yself + (size_t)r * FD);
                ym[tx]      = make_float4(m[0], m[1], m[2], m[3]);
                ym[tx + 16] = make_float4(m[4], m[5], m[6], m[7]);
                ys[tx]      = make_float4(m[0]*s, m[1]*s, m[2]*s, m[3]*s);
                ys[tx + 16] = make_float4(m[4]*s, m[5]*s, m[6]*s, m[7]*s);
            }
        }
        __syncthreads();
    }
}

// ---------------- edge scatter: one warp per edge ----------------
// agg[d] += m'[s] * dinv[d]   (m' already carries dinv[s])
__global__ void scatter_edges(const float4* __restrict__ m4, const int* __restrict__ ei,
                              const float* __restrict__ dinv, float* agg, int E) {
    int gid = blockIdx.x * blockDim.x + threadIdx.x;
    int e = gid >> 5;
    if (e >= E) return;
    int lane = gid & 31;
    int s = __ldg(&ei[e]);
    int d = __ldg(&ei[E + e]);
    float w = __ldg(&dinv[d]);
    float4 v = __ldg(&m4[(size_t)s * 32 + lane]);
    float* a = agg + (size_t)d * FD + lane * 4;
    asm volatile("red.global.add.v4.f32 [%0], {%1,%2,%3,%4};"
                 :: "l"(a), "f"(v.x * w), "f"(v.y * w), "f"(v.z * w), "f"(v.w * w)
                 : "memory");
}

// ---------------- bias + relu (in place) ----------------
__global__ void bias_relu(float* h, const float* __restrict__ b, int n) {
    int idx = blockIdx.x * blockDim.x + threadIdx.x;
    if (idx >= n * 32) return;
    int c4 = idx & 31;
    float4 v = ((float4*)h)[idx];
    float4 bb = ((const float4*)b)[c4];
    v.x = fmaxf(v.x + bb.x, 0.f);
    v.y = fmaxf(v.y + bb.y, 0.f);
    v.z = fmaxf(v.z + bb.z, 0.f);
    v.w = fmaxf(v.w + bb.w, 0.f);
    ((float4*)h)[idx] = v;
}

// ---------------- bias + relu + fused max pool ----------------
__global__ void bias_relu_pool(const float* __restrict__ h, const float* __restrict__ b,
                               const int* __restrict__ batch, float* gpool, int n) {
    int idx = blockIdx.x * blockDim.x + threadIdx.x;
    if (idx >= n * 32) return;
    int node = idx >> 5;
    int c4 = idx & 31;
    float4 v = ((const float4*)h)[idx];
    float4 bb = ((const float4*)b)[c4];
    v.x = fmaxf(v.x + bb.x, 0.f);
    v.y = fmaxf(v.y + bb.y, 0.f);
    v.z = fmaxf(v.z + bb.z, 0.f);
    v.w = fmaxf(v.w + bb.w, 0.f);
    int g = __ldg(&batch[node]);
    int* gp = (int*)(gpool + g * FD + c4 * 4);
    atomicMax(gp + 0, __float_as_int(v.x));   // valid: v >= 0, pool init 0
    atomicMax(gp + 1, __float_as_int(v.y));
    atomicMax(gp + 2, __float_as_int(v.z));
    atomicMax(gp + 3, __float_as_int(v.w));
}

// ---------------- head: relu(g@W3+b3) @ W4 + b4, log_softmax ----------------
__global__ void head(const float* __restrict__ g, const float* __restrict__ W3,
                     const float* __restrict__ b3, const float* __restrict__ W4,
                     const float* __restrict__ b4, float* __restrict__ out) {
    __shared__ float gs[FD];
    __shared__ float red0[4], red1[4];
    int r = blockIdx.x;
    int c = threadIdx.x;
    gs[c] = g[r * FD + c];
    __syncthreads();
    float acc = b3[c];
    #pragma unroll 8
    for (int k = 0; k < FD; k++)
        acc = fmaf(gs[k], W3[k * FD + c], acc);
    float z = acc > 0.f ? acc : 0.f;
    float p0 = z * W4[c * 2 + 0];
    float p1 = z * W4[c * 2 + 1];
    #pragma unroll
    for (int o = 16; o; o >>= 1) {
        p0 += __shfl_down_sync(0xffffffffu, p0, o);
        p1 += __shfl_down_sync(0xffffffffu, p1, o);
    }
    int wid = c >> 5;
    if ((c & 31) == 0) { red0[wid] = p0; red1[wid] = p1; }
    __syncthreads();
    if (c == 0) {
        float l0 = red0[0] + red0[1] + red0[2] + red0[3] + b4[0];
        float l1 = red1[0] + red1[1] + red1[2] + red1[3] + b4[1];
        float mx = fmaxf(l0, l1);
        float lse = mx + logf(expf(l0 - mx) + expf(l1 - mx));
        out[r * 2 + 0] = l0 - lse;
        out[r * 2 + 1] = l1 - lse;
    }
}

extern "C" void kernel_launch(void* const* d_in, const int* in_sizes, int n_in,
                              void* d_out, int out_size) {
    const float* x  = (const float*)d_in[0];
    const float* W1 = (const float*)d_in[1];
    const float* b1 = (const float*)d_in[2];
    const float* W2 = (const float*)d_in[3];
    const float* b2 = (const float*)d_in[4];
    const float* W3 = (const float*)d_in[5];
    const float* b3 = (const float*)d_in[6];
    const float* W4 = (const float*)d_in[7];
    const float* b4 = (const float*)d_in[8];
    const int*   ei = (const int*)d_in[9];
    const int* batch = (const int*)d_in[10];

    int n = in_sizes[0] / FD;
    int E = in_sizes[9] / 2;
    float* out = (float*)d_out;

    float *bufA, *bufB, *bufC, *dinv, *gp;
    cudaGetSymbolAddress((void**)&bufA, d_bufA);
    cudaGetSymbolAddress((void**)&bufB, d_bufB);
    cudaGetSymbolAddress((void**)&bufC, d_bufC);
    cudaGetSymbolAddress((void**)&dinv, d_dinv);
    cudaGetSymbolAddress((void**)&gp,   d_gpool);

    static int sms = 0;
    if (sms == 0) {
        int dev = 0; cudaGetDevice(&dev);
        cudaDeviceGetAttribute(&sms, cudaDevAttrMultiProcessorCount, dev);
        if (sms <= 0) sms = 148;
    }

    const int smem = 3 * 16384 * (int)sizeof(float);   // 192KB
    static int attr_set = 0;
    if (!attr_set) {
        cudaFuncSetAttribute(gemm_dual, cudaFuncAttributeMaxDynamicSharedMemorySize, smem);
        attr_set = 1;
    }

    int ntiles = (n + TR - 1) / TR;
    int gemm_grid = sms < ntiles ? sms : ntiles;

    // degrees -> dinv
    deg_init<<<(n + 255) / 256, 256>>>(dinv, n);
    deg_count<<<(E + 255) / 256, 256>>>(ei + E, dinv, E);
    deg_to_dinv<<<(n + 255) / 256, 256>>>(dinv, n);

    // layer 1: bufA = msg, bufB = self-init -> agg -> h1
    gemm_dual<<<gemm_grid, 256, smem>>>(x, W1, dinv, bufA, bufB, n, ntiles);
    scatter_edges<<<((size_t)E * 32 + 255) / 256, 256>>>((const float4*)bufA, ei, dinv, bufB, E);
    bias_relu<<<(n * 32 + 255) / 256, 256>>>(bufB, b1, n);

    // layer 2: bufA = msg, bufC = self-init -> agg -> relu+pool
    gemm_dual<<<gemm_grid, 256, smem>>>(bufB, W2, dinv, bufA, bufC, n, ntiles);
    cudaMemsetAsync(gp, 0, GG * FD * sizeof(float));
    scatter_edges<<<((size_t)E * 32 + 255) / 256, 256>>>((const float4*)bufA, ei, dinv, bufC, E);
    bias_relu_pool<<<(n * 32 + 255) / 256, 256>>>(bufC, b2, batch, gp, n);

    // head
    head<<<GG, FD>>>(gp, W3, b3, W4, b4, out);
}

// round 5
// speedup vs baseline: 1.1725x; 1.0183x over previous
#include <cuda_runtime.h>
#include <cstdint>
#include <math.h>

#define NMAX 50048
#define FD   128
#define GG   64
#define TR   128    // gemm tile rows

// ---- static scratch (no allocations allowed) ----
__device__ float d_bufA[NMAX * FD];   // messages P = (XW)*dinv[row]
__device__ float d_bufB[NMAX * FD];   // layer-1 agg / h1
__device__ float d_bufC[NMAX * FD];   // layer-2 agg
__device__ float d_dinv[NMAX];
__device__ float d_gpool[GG * FD];

// ---------------- degree / normalization ----------------
__global__ void deg_init(float* deg, int n) {
    int i = blockIdx.x * blockDim.x + threadIdx.x;
    if (i < n) deg[i] = 1.0f;                  // self loop
}
__global__ void deg_count(const int* __restrict__ dst, float* deg, int E) {
    int i = blockIdx.x * blockDim.x + threadIdx.x;
    if (i < E) atomicAdd(&deg[dst[i]], 1.0f);
}
__global__ void deg_to_dinv(float* deg, int n) {
    int i = blockIdx.x * blockDim.x + threadIdx.x;
    if (i < n) deg[i] = rsqrtf(deg[i]);
}

// ---------------- GEMM: P[r,:] = (X[r,:] @ W) * dinv[r], written to TWO buffers ----
// 128-row tiles, 256 threads, 8 rows x 8 cols per thread (cols tx*4, tx*4+64),
// W persistent in smem, X double-buffered via cp.async, fma.rn.f32x2.
__device__ __forceinline__ void load_tileX(float* dst, const float* X, int row0, int n) {
    int rows = n - row0;
    #pragma unroll
    for (int t = 0; t < 16; t++) {
        int idx = threadIdx.x + t * 256;      // float4 index in 128x128 tile
        int r = idx >> 5;
        if (r < rows) {
            unsigned int sa = (unsigned int)__cvta_generic_to_shared(dst + idx * 4);
            const float4* g = (const float4*)X + (size_t)(row0 + r) * 32 + (idx & 31);
            asm volatile("cp.async.cg.shared.global [%0], [%1], 16;\n" :: "r"(sa), "l"(g));
        }
    }
    asm volatile("cp.async.commit_group;\n" ::: "memory");
}

__global__ void __launch_bounds__(256, 1)
gemm_dual(const float* __restrict__ X, const float* __restrict__ W,
          const float* __restrict__ dinv, float* __restrict__ Ymsg,
          float* __restrict__ Yagg, int n, int ntiles) {
    extern __shared__ float sh[];
    float* Wsh = sh;                          // 64KB
    float* Xb0 = sh + 16384;                  // 64KB
    float* Xb1 = sh + 32768;                  // 64KB

    for (int i = threadIdx.x; i < 16384; i += 256) Wsh[i] = W[i];

    const int tx = threadIdx.x & 15;
    const int ty = threadIdx.x >> 4;
    const int cA = tx * 4;                    // conflict-free 16B stride across tx
    const int cB = cA + 64;
    const int r0 = ty * 8;

    if (blockIdx.x < ntiles) load_tileX(Xb0, X, blockIdx.x * TR, n);

    int p = 0;
    for (int tile = blockIdx.x; tile < ntiles; tile += gridDim.x, p ^= 1) {
        float* cur = p ? Xb1 : Xb0;
        float* nxt = p ? Xb0 : Xb1;
        int nt = tile + gridDim.x;
        if (nt < ntiles) load_tileX(nxt, X, nt * TR, n);
        else asm volatile("cp.async.commit_group;\n" ::: "memory");
        asm volatile("cp.async.wait_group 1;\n" ::: "memory");
        __syncthreads();

        unsigned long long acc[8][4];
        #pragma unroll
        for (int j = 0; j < 8; j++)
            #pragma unroll
            for (int q = 0; q < 4; q++) acc[j][q] = 0ull;

        #pragma unroll 4
        for (int k4 = 0; k4 < FD; k4 += 4) {
            float4 xv[8];
            #pragma unroll
            for (int j = 0; j < 8; j++)
                xv[j] = *(const float4*)(cur + (r0 + j) * FD + k4);
            #pragma unroll
            for (int kk = 0; kk < 4; kk++) {
                const float* wrow = Wsh + (k4 + kk) * FD;
                ulonglong2 wA = *(const ulonglong2*)(wrow + cA);
                ulonglong2 wB = *(const ulonglong2*)(wrow + cB);
                #pragma unroll
                for (int j = 0; j < 8; j++) {
                    float xs = (kk == 0) ? xv[j].x : (kk == 1) ? xv[j].y
                             : (kk == 2) ? xv[j].z : xv[j].w;
                    unsigned int xb = __float_as_uint(xs);
                    unsigned long long xd;
                    asm("mov.b64 %0, {%1, %1};" : "=l"(xd) : "r"(xb));
                    asm("fma.rn.f32x2 %0, %1, %2, %0;" : "+l"(acc[j][0]) : "l"(xd), "l"(wA.x));
                    asm("fma.rn.f32x2 %0, %1, %2, %0;" : "+l"(acc[j][1]) : "l"(xd), "l"(wA.y));
                    asm("fma.rn.f32x2 %0, %1, %2, %0;" : "+l"(acc[j][2]) : "l"(xd), "l"(wB.x));
                    asm("fma.rn.f32x2 %0, %1, %2, %0;" : "+l"(acc[j][3]) : "l"(xd), "l"(wB.y));
                }
            }
        }

        int row0 = tile * TR;
        #pragma unroll
        for (int j = 0; j < 8; j++) {
            int r = row0 + r0 + j;
            if (r < n) {
                float s = __ldg(&dinv[r]);
                float m[8];
                #pragma unroll
                for (int q = 0; q < 4; q++) {
                    m[2*q]   = __uint_as_float((unsigned int)acc[j][q]) * s;
                    m[2*q+1] = __uint_as_float((unsigned int)(acc[j][q] >> 32)) * s;
                }
                float4 v0 = make_float4(m[0], m[1], m[2], m[3]);
                float4 v1 = make_float4(m[4], m[5], m[6], m[7]);
                float4* ym = (float4*)(Ymsg + (size_t)r * FD);
                float4* ya = (float4*)(Yagg + (size_t)r * FD);
                ym[tx]      = v0;  ym[tx + 16] = v1;
                ya[tx]      = v0;  ya[tx + 16] = v1;   // agg init = self msg
            }
        }
        __syncthreads();
    }
}

// ---------------- edge scatter: one warp per edge, minimal chain ----------------
// agg[d] += P[s]
__global__ void scatter_edges(const float4* __restrict__ m4, const int* __restrict__ ei,
                              float* agg, int E) {
    int gid = blockIdx.x * blockDim.x + threadIdx.x;
    int e = gid >> 5;
    if (e >= E) return;
    int lane = gid & 31;
    int s = __ldg(&ei[e]);
    int d = __ldg(&ei[E + e]);
    float4 v = __ldg(&m4[(size_t)s * 32 + lane]);
    float* a = agg + (size_t)d * FD + lane * 4;
    asm volatile("red.global.add.v4.f32 [%0], {%1,%2,%3,%4};"
                 :: "l"(a), "f"(v.x), "f"(v.y), "f"(v.z), "f"(v.w)
                 : "memory");
}

// ---------------- h = relu(dinv[node]*agg + b) ----------------
__global__ void bias_relu(const float* __restrict__ agg, const float* __restrict__ dinv,
                          const float* __restrict__ b, float* __restrict__ h, int n) {
    int idx = blockIdx.x * blockDim.x + threadIdx.x;
    if (idx >= n * 32) return;
    int node = idx >> 5;
    int c4 = idx & 31;
    float dd = __ldg(&dinv[node]);
    float4 v = ((const float4*)agg)[idx];
    float4 bb = ((const float4*)b)[c4];
    v.x = fmaxf(fmaf(v.x, dd, bb.x), 0.f);
    v.y = fmaxf(fmaf(v.y, dd, bb.y), 0.f);
    v.z = fmaxf(fmaf(v.z, dd, bb.z), 0.f);
    v.w = fmaxf(fmaf(v.w, dd, bb.w), 0.f);
    ((float4*)h)[idx] = v;
}

// ---------------- final layer: relu + fused max pool ----------------
__global__ void bias_relu_pool(const float* __restrict__ agg, const float* __restrict__ dinv,
                               const float* __restrict__ b, const int* __restrict__ batch,
                               float* gpool, int n) {
    int idx = blockIdx.x * blockDim.x + threadIdx.x;
    if (idx >= n * 32) return;
    int node = idx >> 5;
    int c4 = idx & 31;
    float dd = __ldg(&dinv[node]);
    float4 v = ((const float4*)agg)[idx];
    float4 bb = ((const float4*)b)[c4];
    v.x = fmaxf(fmaf(v.x, dd, bb.x), 0.f);
    v.y = fmaxf(fmaf(v.y, dd, bb.y), 0.f);
    v.z = fmaxf(fmaf(v.z, dd, bb.z), 0.f);
    v.w = fmaxf(fmaf(v.w, dd, bb.w), 0.f);
    int g = __ldg(&batch[node]);
    int* gp = (int*)(gpool + g * FD + c4 * 4);
    atomicMax(gp + 0, __float_as_int(v.x));   // valid: v >= 0, pool init 0
    atomicMax(gp + 1, __float_as_int(v.y));
    atomicMax(gp + 2, __float_as_int(v.z));
    atomicMax(gp + 3, __float_as_int(v.w));
}

// ---------------- head: relu(g@W3+b3) @ W4 + b4, log_softmax ----------------
__global__ void head(const float* __restrict__ g, const float* __restrict__ W3,
                     const float* __restrict__ b3, const float* __restrict__ W4,
                     const float* __restrict__ b4, float* __restrict__ out) {
    __shared__ float gs[FD];
    __shared__ float red0[4], red1[4];
    int r = blockIdx.x;
    int c = threadIdx.x;
    gs[c] = g[r * FD + c];
    __syncthreads();
    float acc = b3[c];
    #pragma unroll 8
    for (int k = 0; k < FD; k++)
        acc = fmaf(gs[k], W3[k * FD + c], acc);
    float z = acc > 0.f ? acc : 0.f;
    float p0 = z * W4[c * 2 + 0];
    float p1 = z * W4[c * 2 + 1];
    #pragma unroll
    for (int o = 16; o; o >>= 1) {
        p0 += __shfl_down_sync(0xffffffffu, p0, o);
        p1 += __shfl_down_sync(0xffffffffu, p1, o);
    }
    int wid = c >> 5;
    if ((c & 31) == 0) { red0[wid] = p0; red1[wid] = p1; }
    __syncthreads();
    if (c == 0) {
        float l0 = red0[0] + red0[1] + red0[2] + red0[3] + b4[0];
        float l1 = red1[0] + red1[1] + red1[2] + red1[3] + b4[1];
        float mx = fmaxf(l0, l1);
        float lse = mx + logf(expf(l0 - mx) + expf(l1 - mx));
        out[r * 2 + 0] = l0 - lse;
        out[r * 2 + 1] = l1 - lse;
    }
}

extern "C" void kernel_launch(void* const* d_in, const int* in_sizes, int n_in,
                              void* d_out, int out_size) {
    const float* x  = (const float*)d_in[0];
    const float* W1 = (const float*)d_in[1];
    const float* b1 = (const float*)d_in[2];
    const float* W2 = (const float*)d_in[3];
    const float* b2 = (const float*)d_in[4];
    const float* W3 = (const float*)d_in[5];
    const float* b3 = (const float*)d_in[6];
    const float* W4 = (const float*)d_in[7];
    const float* b4 = (const float*)d_in[8];
    const int*   ei = (const int*)d_in[9];
    const int* batch = (const int*)d_in[10];

    int n = in_sizes[0] / FD;
    int E = in_sizes[9] / 2;
    float* out = (float*)d_out;

    float *bufA, *bufB, *bufC, *dinv, *gp;
    cudaGetSymbolAddress((void**)&bufA, d_bufA);
    cudaGetSymbolAddress((void**)&bufB, d_bufB);
    cudaGetSymbolAddress((void**)&bufC, d_bufC);
    cudaGetSymbolAddress((void**)&dinv, d_dinv);
    cudaGetSymbolAddress((void**)&gp,   d_gpool);

    static int sms = 0;
    if (sms == 0) {
        int dev = 0; cudaGetDevice(&dev);
        cudaDeviceGetAttribute(&sms, cudaDevAttrMultiProcessorCount, dev);
        if (sms <= 0) sms = 148;
    }

    const int smem = 3 * 16384 * (int)sizeof(float);   // 192KB
    static int attr_set = 0;
    if (!attr_set) {
        cudaFuncSetAttribute(gemm_dual, cudaFuncAttributeMaxDynamicSharedMemorySize, smem);
        attr_set = 1;
    }

    int ntiles = (n + TR - 1) / TR;
    int gemm_grid = sms < ntiles ? sms : ntiles;

    // degrees -> dinv
    deg_init<<<(n + 255) / 256, 256>>>(dinv, n);
    deg_count<<<(E + 255) / 256, 256>>>(ei + E, dinv, E);
    deg_to_dinv<<<(n + 255) / 256, 256>>>(dinv, n);

    // layer 1: bufA = P, bufB = P (agg init) -> scatter -> h1 in bufB
    gemm_dual<<<gemm_grid, 256, smem>>>(x, W1, dinv, bufA, bufB, n, ntiles);
    scatter_edges<<<((size_t)E * 32 + 255) / 256, 256>>>((const float4*)bufA, ei, bufB, E);
    bias_relu<<<(n * 32 + 255) / 256, 256>>>(bufB, dinv, b1, bufB, n);

    // layer 2: bufA = P, bufC = agg -> relu+pool
    gemm_dual<<<gemm_grid, 256, smem>>>(bufB, W2, dinv, bufA, bufC, n, ntiles);
    cudaMemsetAsync(gp, 0, GG * FD * sizeof(float));
    scatter_edges<<<((size_t)E * 32 + 255) / 256, 256>>>((const float4*)bufA, ei, bufC, E);
    bias_relu_pool<<<(n * 32 + 255) / 256, 256>>>(bufC, dinv, b2, batch, gp, n);

    // head
    head<<<GG, FD>>>(gp, W3, b3, W4, b4, out);
}